// round 1
// baseline (speedup 1.0000x reference)
#include <cuda_runtime.h>
#include <math.h>

#define T_STEPS 32
#define BATCH   128
#define NQ      8

// scratch: qx[t, b, j] = sum_k W[j,k]*x[t,b,k] + b[j]   (j = 0..7; only first 8 rows of W used)
__device__ float g_qx[T_STEPS * BATCH * NQ];

// ---------------------------------------------------------------------------
// Kernel 1: precompute data-dependent part of qvec for all (t, b) in parallel
// grid = 512 blocks * 64 threads; each block handles 8 rows of [T*B, 64]
// ---------------------------------------------------------------------------
__global__ void qx_kernel(const float* __restrict__ x,
                          const float* __restrict__ W,
                          const float* __restrict__ bv) {
    __shared__ float sx[8 * 65];
    __shared__ float sW[8 * 65];
    __shared__ float sb[8];
    int tid  = threadIdx.x;           // 0..63
    int row0 = blockIdx.x * 8;        // row = t*BATCH + b

    for (int i = tid; i < 512; i += 64) {
        int r = i >> 6, k = i & 63;
        sx[r * 65 + k] = x[(row0 + r) * 64 + k];
        sW[r * 65 + k] = W[r * 72 + k];     // W row stride = 72 (D+N)
    }
    if (tid < 8) sb[tid] = bv[tid];
    __syncthreads();

    int row = tid >> 3, j = tid & 7;
    const float* wr = &sW[j * 65];
    const float* xr = &sx[row * 65];
    float acc = sb[j];
    #pragma unroll
    for (int k = 0; k < 64; ++k) acc += wr[k] * xr[k];
    g_qx[(row0 + row) * 8 + j] = acc;
}

// ---------------------------------------------------------------------------
// warp-level quantum circuit helpers
// amplitude index idx = r*32 + lane   (r = register 0..7, lane = 0..31)
// wire w <-> bit (7-w) of idx; bits 5..7 are register bits, 0..4 lane bits
// ---------------------------------------------------------------------------

__device__ __forceinline__ void ry_pair(float& lr, float& li, float& hr, float& hi2,
                                        float c, float s) {
    float a = lr, b = li, d = hr, e = hi2;
    lr = c * a - s * d;  li = c * b - s * e;
    hr = s * a + c * d;  hi2 = s * b + c * e;
}

template <int LM>
__device__ __forceinline__ void ry_lane(float (&ar)[8], float (&ai)[8], int lane,
                                        float c, float s) {
    float tt = (lane & LM) ? s : -s;
    #pragma unroll
    for (int r = 0; r < 8; ++r) {
        float pr = __shfl_xor_sync(0xffffffffu, ar[r], LM);
        float pi = __shfl_xor_sync(0xffffffffu, ai[r], LM);
        ar[r] = c * ar[r] + tt * pr;
        ai[r] = c * ai[r] + tt * pi;
    }
}

// CNOT: ctrl = lane bit CM, tgt = lane bit TM
template <int CM, int TM>
__device__ __forceinline__ void cnot_ll(float (&ar)[8], float (&ai)[8], int lane) {
    bool p = (lane & CM) != 0;
    #pragma unroll
    for (int r = 0; r < 8; ++r) {
        float pr = __shfl_xor_sync(0xffffffffu, ar[r], TM);
        float pi = __shfl_xor_sync(0xffffffffu, ai[r], TM);
        ar[r] = p ? pr : ar[r];
        ai[r] = p ? pi : ai[r];
    }
}

__device__ __forceinline__ void swap_regs(float& a, float& b) {
    float t = a; a = b; b = t;
}

__device__ __forceinline__ float sigmoidf_(float v) {
    return 1.0f / (1.0f + expf(-v));
}

// ---------------------------------------------------------------------------
// Kernel 2: per-batch sequential QLSTM.
// 128 blocks (one per batch lane) * 128 threads (warp c = circuit c:
// 0=forget, 1=input, 2=update, 3=output).
// ---------------------------------------------------------------------------
__global__ void __launch_bounds__(128, 1) qlstm_kernel(
    const float* __restrict__ W,
    const float* __restrict__ fp, const float* __restrict__ ip,
    const float* __restrict__ up, const float* __restrict__ op,
    float* __restrict__ out) {

    __shared__ float sh_h[8], sh_c[8], sh_qc[8], sh_qs[8];
    __shared__ float sh_e[4][8];
    __shared__ float sWh[8][8];

    int tid  = threadIdx.x;
    int lane = tid & 31;
    int cid  = tid >> 5;
    int b    = blockIdx.x;

    if (tid < 64) sWh[tid >> 3][tid & 7] = W[(tid >> 3) * 72 + 64 + (tid & 7)];
    if (tid < 8) { sh_h[tid] = 0.f; sh_c[tid] = 0.f; }

    // per-circuit variational RY angles: cos/sin(param/2), constant over time
    const float* P = (cid == 0) ? fp : (cid == 1) ? ip : (cid == 2) ? up : op;
    float pc[8], ps[8];
    #pragma unroll
    for (int w = 0; w < 8; ++w) {
        float s, c; sincosf(0.5f * P[w], &s, &c);
        pc[w] = c; ps[w] = s;
    }

    for (int t = 0; t < T_STEPS; ++t) {
        __syncthreads();  // h, c stable

        // qvec angle j = qx[t,b,j] + Wh[j,:] . h ; encode cos/sin(angle/2)
        if (tid < 8) {
            float th = g_qx[(t * BATCH + b) * 8 + tid];
            #pragma unroll
            for (int k = 0; k < 8; ++k) th += sWh[tid][k] * sh_h[k];
            float s, c; sincosf(0.5f * th, &s, &c);
            sh_qs[tid] = s; sh_qc[tid] = c;
        }
        __syncthreads();

        float qc[8], qs[8];
        #pragma unroll
        for (int w = 0; w < 8; ++w) { qc[w] = sh_qc[w]; qs[w] = sh_qs[w]; }

        // ---- RX encoding layer in closed form: product state ----
        // amp(idx) = M(idx) * (-i)^popcount(idx),  M = prod(bit ? sin : cos)
        float mLo = 1.f;
        mLo *= (lane & 1)  ? qs[7] : qc[7];
        mLo *= (lane & 2)  ? qs[6] : qc[6];
        mLo *= (lane & 4)  ? qs[5] : qc[5];
        mLo *= (lane & 8)  ? qs[4] : qc[4];
        mLo *= (lane & 16) ? qs[3] : qc[3];
        int pcl = __popc(lane);

        float ar[8], ai[8];
        #pragma unroll
        for (int r = 0; r < 8; ++r) {
            float mHi = ((r & 1) ? qs[2] : qc[2]) *
                        ((r & 2) ? qs[1] : qc[1]) *
                        ((r & 4) ? qs[0] : qc[0]);
            float M = mLo * mHi;
            int k = (pcl + __popc(r)) & 3;
            ar[r] = (k == 0) ? M : ((k == 2) ? -M : 0.f);
            ai[r] = (k == 1) ? -M : ((k == 3) ? M : 0.f);
        }

        // ---- variational layer: RY(w) then CNOT(w, (w+1)%8), w = 0..7 ----

        // w=0: RY on bit7 (reg pairs r, r+4)
        ry_pair(ar[0], ai[0], ar[4], ai[4], pc[0], ps[0]);
        ry_pair(ar[1], ai[1], ar[5], ai[5], pc[0], ps[0]);
        ry_pair(ar[2], ai[2], ar[6], ai[6], pc[0], ps[0]);
        ry_pair(ar[3], ai[3], ar[7], ai[7], pc[0], ps[0]);
        // CNOT(0,1): ctrl bit7, tgt bit6 -> swap (4,6),(5,7)
        swap_regs(ar[4], ar[6]); swap_regs(ai[4], ai[6]);
        swap_regs(ar[5], ar[7]); swap_regs(ai[5], ai[7]);

        // w=1: RY on bit6 (reg pairs r, r+2)
        ry_pair(ar[0], ai[0], ar[2], ai[2], pc[1], ps[1]);
        ry_pair(ar[1], ai[1], ar[3], ai[3], pc[1], ps[1]);
        ry_pair(ar[4], ai[4], ar[6], ai[6], pc[1], ps[1]);
        ry_pair(ar[5], ai[5], ar[7], ai[7], pc[1], ps[1]);
        // CNOT(1,2): ctrl bit6, tgt bit5 -> swap (2,3),(6,7)
        swap_regs(ar[2], ar[3]); swap_regs(ai[2], ai[3]);
        swap_regs(ar[6], ar[7]); swap_regs(ai[6], ai[7]);

        // w=2: RY on bit5 (reg pairs r, r+1)
        ry_pair(ar[0], ai[0], ar[1], ai[1], pc[2], ps[2]);
        ry_pair(ar[2], ai[2], ar[3], ai[3], pc[2], ps[2]);
        ry_pair(ar[4], ai[4], ar[5], ai[5], pc[2], ps[2]);
        ry_pair(ar[6], ai[6], ar[7], ai[7], pc[2], ps[2]);
        // CNOT(2,3): ctrl bit5 (odd r), tgt lane bit4 -> exchange across lanes
        ar[1] = __shfl_xor_sync(0xffffffffu, ar[1], 16);
        ai[1] = __shfl_xor_sync(0xffffffffu, ai[1], 16);
        ar[3] = __shfl_xor_sync(0xffffffffu, ar[3], 16);
        ai[3] = __shfl_xor_sync(0xffffffffu, ai[3], 16);
        ar[5] = __shfl_xor_sync(0xffffffffu, ar[5], 16);
        ai[5] = __shfl_xor_sync(0xffffffffu, ai[5], 16);
        ar[7] = __shfl_xor_sync(0xffffffffu, ar[7], 16);
        ai[7] = __shfl_xor_sync(0xffffffffu, ai[7], 16);

        // w=3: RY on lane bit4; CNOT(3,4): ctrl lane16, tgt lane8
        ry_lane<16>(ar, ai, lane, pc[3], ps[3]);
        cnot_ll<16, 8>(ar, ai, lane);

        // w=4
        ry_lane<8>(ar, ai, lane, pc[4], ps[4]);
        cnot_ll<8, 4>(ar, ai, lane);

        // w=5
        ry_lane<4>(ar, ai, lane, pc[5], ps[5]);
        cnot_ll<4, 2>(ar, ai, lane);

        // w=6
        ry_lane<2>(ar, ai, lane, pc[6], ps[6]);
        cnot_ll<2, 1>(ar, ai, lane);

        // w=7: RY on lane bit0; CNOT(7,0): ctrl lane bit0, tgt bit7 (reg r<->r+4)
        ry_lane<1>(ar, ai, lane, pc[7], ps[7]);
        {
            bool p = (lane & 1) != 0;
            #pragma unroll
            for (int r = 0; r < 4; ++r) {
                float t0 = ar[r], t1 = ai[r];
                ar[r]     = p ? ar[r + 4] : ar[r];
                ai[r]     = p ? ai[r + 4] : ai[r];
                ar[r + 4] = p ? t0 : ar[r + 4];
                ai[r + 4] = p ? t1 : ai[r + 4];
            }
        }

        // ---- <Z_w> expectations ----
        float p0 = ar[0]*ar[0] + ai[0]*ai[0];
        float p1 = ar[1]*ar[1] + ai[1]*ai[1];
        float p2 = ar[2]*ar[2] + ai[2]*ai[2];
        float p3 = ar[3]*ar[3] + ai[3]*ai[3];
        float p4 = ar[4]*ar[4] + ai[4]*ai[4];
        float p5 = ar[5]*ar[5] + ai[5]*ai[5];
        float p6 = ar[6]*ar[6] + ai[6]*ai[6];
        float p7 = ar[7]*ar[7] + ai[7]*ai[7];
        float S  = p0 + p1 + p2 + p3 + p4 + p5 + p6 + p7;

        float e[8];
        e[0] = (p0 + p1 + p2 + p3) - (p4 + p5 + p6 + p7);  // bit7 = r bit2
        e[1] = (p0 + p1 + p4 + p5) - (p2 + p3 + p6 + p7);  // bit6 = r bit1
        e[2] = (p0 + p2 + p4 + p6) - (p1 + p3 + p5 + p7);  // bit5 = r bit0
        e[3] = (lane & 16) ? -S : S;
        e[4] = (lane & 8)  ? -S : S;
        e[5] = (lane & 4)  ? -S : S;
        e[6] = (lane & 2)  ? -S : S;
        e[7] = (lane & 1)  ? -S : S;

        #pragma unroll
        for (int m = 16; m; m >>= 1) {
            #pragma unroll
            for (int k = 0; k < 8; ++k)
                e[k] += __shfl_xor_sync(0xffffffffu, e[k], m);
        }
        if (lane == 0) {
            #pragma unroll
            for (int k = 0; k < 8; ++k) sh_e[cid][k] = e[k];
        }
        __syncthreads();

        // ---- LSTM cell update ----
        if (tid < 8) {
            float f = sigmoidf_(sh_e[0][tid]);
            float i = sigmoidf_(sh_e[1][tid]);
            float g = tanhf(sh_e[2][tid]);
            float o = sigmoidf_(sh_e[3][tid]);
            float cn = f * sh_c[tid] + i * g;
            float hn = o * tanhf(cn);
            sh_c[tid] = cn;
            sh_h[tid] = hn;
            out[(t * BATCH + b) * NQ + tid] = hn;
        }
    }

    __syncthreads();
    if (tid < 8) {
        out[T_STEPS * BATCH * NQ + b * NQ + tid]              = sh_h[tid];  // hx
        out[T_STEPS * BATCH * NQ + BATCH * NQ + b * NQ + tid] = sh_c[tid];  // cx
    }
}

// ---------------------------------------------------------------------------
extern "C" void kernel_launch(void* const* d_in, const int* in_sizes, int n_in,
                              void* d_out, int out_size) {
    const float* x  = (const float*)d_in[0];  // inputs [32,128,64]
    const float* W  = (const float*)d_in[1];  // [16,72]
    const float* bv = (const float*)d_in[2];  // [16]
    const float* fp = (const float*)d_in[3];  // forget_params [8]
    const float* ip = (const float*)d_in[4];  // input_params  [8]
    const float* up = (const float*)d_in[5];  // update_params [8]
    const float* op = (const float*)d_in[6];  // output_params [8]
    float* out = (float*)d_out;

    qx_kernel<<<(T_STEPS * BATCH) / 8, 64>>>(x, W, bv);
    qlstm_kernel<<<BATCH, 128>>>(W, fp, ip, up, op, out);
}

// round 2
// speedup vs baseline: 1.3646x; 1.3646x over previous
#include <cuda_runtime.h>
#include <math.h>

#define T_STEPS 32
#define BATCH   128
#define NQ      8
#define FULL    0xffffffffu

// scratch: qx[t, b, j] = sum_k W[j,k]*x[t,b,k] + b[j]   (j = 0..7)
__device__ float g_qx[T_STEPS * BATCH * NQ];

// ---------------------------------------------------------------------------
// Kernel 1: precompute data-dependent part of qvec for all (t, b) in parallel
// ---------------------------------------------------------------------------
__global__ void qx_kernel(const float* __restrict__ x,
                          const float* __restrict__ W,
                          const float* __restrict__ bv) {
    __shared__ float sx[8 * 65];
    __shared__ float sW[8 * 65];
    __shared__ float sb[8];
    int tid  = threadIdx.x;           // 0..63
    int row0 = blockIdx.x * 8;        // row = t*BATCH + b

    for (int i = tid; i < 512; i += 64) {
        int r = i >> 6, k = i & 63;
        sx[r * 65 + k] = x[(row0 + r) * 64 + k];
        sW[r * 65 + k] = W[r * 72 + k];     // W row stride = 72 (D+N)
    }
    if (tid < 8) sb[tid] = bv[tid];
    __syncthreads();

    int row = tid >> 3, j = tid & 7;
    const float* wr = &sW[j * 65];
    const float* xr = &sx[row * 65];
    float acc = sb[j];
    #pragma unroll
    for (int k = 0; k < 64; ++k) acc += wr[k] * xr[k];
    g_qx[(row0 + row) * 8 + j] = acc;
}

// ---------------------------------------------------------------------------
// warp-level circuit helpers
// amplitude index idx = r*32 + lane; wire w <-> bit (7-w) of idx
// r bits 2,1,0 = wires 0,1,2 ; lane bits 16,8,4,2,1 = wires 3,4,5,6,7
// ---------------------------------------------------------------------------

__device__ __forceinline__ void ry_pair(float& lr, float& li, float& hr, float& hi2,
                                        float c, float s) {
    float a = lr, b = li, d = hr, e = hi2;
    lr = c * a - s * d;  li = c * b - s * e;
    hr = s * a + c * d;  hi2 = s * b + c * e;
}

// fused: CNOT(ctrl = lane bit CM, tgt = lane bit TM) followed by RY on bit TM
template <int CM, int TM>
__device__ __forceinline__ void fused_cnot_ry(float (&ar)[8], float (&ai)[8],
                                              int lane, float c, float s) {
    float tt = (lane & TM) ? s : -s;
    bool cm = (lane & CM) != 0;
    #pragma unroll
    for (int r = 0; r < 8; ++r) {
        float pr = __shfl_xor_sync(FULL, ar[r], TM);
        float pi = __shfl_xor_sync(FULL, ai[r], TM);
        float ownr = cm ? pr : ar[r];
        float othr = cm ? ar[r] : pr;
        float owni = cm ? pi : ai[r];
        float othi = cm ? ai[r] : pi;
        ar[r] = c * ownr + tt * othr;
        ai[r] = c * owni + tt * othi;
    }
}

// fused: CNOT(ctrl = reg bit0 (odd r), tgt = lane bit 16) followed by RY on lane16
__device__ __forceinline__ void fused_cnot_regctrl_ry16(float (&ar)[8], float (&ai)[8],
                                                        int lane, float c, float s) {
    float tt = (lane & 16) ? s : -s;
    #pragma unroll
    for (int r = 0; r < 8; ++r) {
        float pr = __shfl_xor_sync(FULL, ar[r], 16);
        float pi = __shfl_xor_sync(FULL, ai[r], 16);
        if (r & 1) {   // ctrl set: roles swapped (compile-time)
            ar[r] = c * pr + tt * ar[r];
            ai[r] = c * pi + tt * ai[r];
        } else {
            ar[r] = c * ar[r] + tt * pr;
            ai[r] = c * ai[r] + tt * pi;
        }
    }
}

__device__ __forceinline__ void swap_regs(float& a, float& b) {
    float t = a; a = b; b = t;
}

__device__ __forceinline__ float fast_sigmoid(float v) {
    return __fdividef(1.0f, 1.0f + __expf(-v));
}
__device__ __forceinline__ float fast_tanh(float v) {
    return __fdividef(2.0f, 1.0f + __expf(-2.0f * v)) - 1.0f;
}

// ---------------------------------------------------------------------------
// Kernel 2: per-batch sequential QLSTM. 128 blocks x 128 threads.
// warp cid = circuit (0=forget, 1=input, 2=update, 3=output).
// h, c live in per-warp registers: lane group g = (lane>>2)&7 holds h[g], c[g].
// One __syncthreads per step (double-buffered expectation exchange).
// ---------------------------------------------------------------------------
__global__ void __launch_bounds__(128, 1) qlstm_kernel(
    const float* __restrict__ W,
    const float* __restrict__ fp, const float* __restrict__ ip,
    const float* __restrict__ up, const float* __restrict__ op,
    float* __restrict__ out) {

    __shared__ float sh_e[2][4][8];

    int tid  = threadIdx.x;
    int lane = tid & 31;
    int cid  = tid >> 5;
    int b    = blockIdx.x;
    int j    = lane & 7;          // angle row this lane computes
    int g    = (lane >> 2) & 7;   // e-index / h-index this lane owns after reduce

    // Wh row j in registers
    float wh[8];
    #pragma unroll
    for (int k = 0; k < 8; ++k) wh[k] = W[j * 72 + 64 + k];

    // per-circuit variational RY cos/sin (constant over time)
    const float* P = (cid == 0) ? fp : (cid == 1) ? ip : (cid == 2) ? up : op;
    float pc[8], ps[8];
    #pragma unroll
    for (int w = 0; w < 8; ++w) {
        float s, c; sincosf(0.5f * P[w], &s, &c);
        pc[w] = c; ps[w] = s;
    }

    float h_reg = 0.f, c_reg = 0.f;
    float qx_cur = g_qx[b * 8 + j];   // t = 0

    #pragma unroll 1
    for (int t = 0; t < T_STEPS; ++t) {
        // ---- angles: th_j = qx_j + Wh[j,:] . h ----
        float th = qx_cur;
        #pragma unroll
        for (int k = 0; k < 8; ++k) {
            float hk = __shfl_sync(FULL, h_reg, 4 * k);
            th += wh[k] * hk;
        }
        float s0, c0;
        __sincosf(0.5f * th, &s0, &c0);
        float qc[8], qs[8];
        #pragma unroll
        for (int w = 0; w < 8; ++w) {
            qc[w] = __shfl_sync(FULL, c0, w);
            qs[w] = __shfl_sync(FULL, s0, w);
        }

        // prefetch next step's qx
        int tn = (t + 1 < T_STEPS) ? (t + 1) : t;
        qx_cur = g_qx[(tn * BATCH + b) * 8 + j];

        // ---- RX encoding: product state, amp(idx) = M * (-i)^popcount ----
        float mLo = 1.f;
        mLo *= (lane & 1)  ? qs[7] : qc[7];
        mLo *= (lane & 2)  ? qs[6] : qc[6];
        mLo *= (lane & 4)  ? qs[5] : qc[5];
        mLo *= (lane & 8)  ? qs[4] : qc[4];
        mLo *= (lane & 16) ? qs[3] : qc[3];
        int pcl = __popc(lane);

        float ar[8], ai[8];
        #pragma unroll
        for (int r = 0; r < 8; ++r) {
            float mHi = ((r & 1) ? qs[2] : qc[2]) *
                        ((r & 2) ? qs[1] : qc[1]) *
                        ((r & 4) ? qs[0] : qc[0]);
            float M = mLo * mHi;
            int k = (pcl + __popc(r)) & 3;
            ar[r] = (k == 0) ? M : ((k == 2) ? -M : 0.f);
            ai[r] = (k == 1) ? -M : ((k == 3) ? M : 0.f);
        }

        // ---- variational layer ----
        // w=0: RY reg bit2; CNOT(0,1) swap (4,6),(5,7)
        ry_pair(ar[0], ai[0], ar[4], ai[4], pc[0], ps[0]);
        ry_pair(ar[1], ai[1], ar[5], ai[5], pc[0], ps[0]);
        ry_pair(ar[2], ai[2], ar[6], ai[6], pc[0], ps[0]);
        ry_pair(ar[3], ai[3], ar[7], ai[7], pc[0], ps[0]);
        swap_regs(ar[4], ar[6]); swap_regs(ai[4], ai[6]);
        swap_regs(ar[5], ar[7]); swap_regs(ai[5], ai[7]);

        // w=1: RY reg bit1; CNOT(1,2) swap (2,3),(6,7)
        ry_pair(ar[0], ai[0], ar[2], ai[2], pc[1], ps[1]);
        ry_pair(ar[1], ai[1], ar[3], ai[3], pc[1], ps[1]);
        ry_pair(ar[4], ai[4], ar[6], ai[6], pc[1], ps[1]);
        ry_pair(ar[5], ai[5], ar[7], ai[7], pc[1], ps[1]);
        swap_regs(ar[2], ar[3]); swap_regs(ai[2], ai[3]);
        swap_regs(ar[6], ar[7]); swap_regs(ai[6], ai[7]);

        // w=2: RY reg bit0; CNOT(2,3) fused into next gate
        ry_pair(ar[0], ai[0], ar[1], ai[1], pc[2], ps[2]);
        ry_pair(ar[2], ai[2], ar[3], ai[3], pc[2], ps[2]);
        ry_pair(ar[4], ai[4], ar[5], ai[5], pc[2], ps[2]);
        ry_pair(ar[6], ai[6], ar[7], ai[7], pc[2], ps[2]);

        // w=3: [CNOT(2,3) ctrl odd-r] + RY lane16 ; CNOT(3,4) fused onward
        fused_cnot_regctrl_ry16(ar, ai, lane, pc[3], ps[3]);
        // w=4: [CNOT(3,4) ctrl16] + RY lane8
        fused_cnot_ry<16, 8>(ar, ai, lane, pc[4], ps[4]);
        // w=5
        fused_cnot_ry<8, 4>(ar, ai, lane, pc[5], ps[5]);
        // w=6
        fused_cnot_ry<4, 2>(ar, ai, lane, pc[6], ps[6]);
        // w=7
        fused_cnot_ry<2, 1>(ar, ai, lane, pc[7], ps[7]);
        // CNOT(7,0): ctrl lane bit0, tgt reg bit2 -> folded into e[0] sign below

        // ---- <Z_w> partials ----
        float q0 = ar[0]*ar[0] + ai[0]*ai[0];
        float q1 = ar[1]*ar[1] + ai[1]*ai[1];
        float q2 = ar[2]*ar[2] + ai[2]*ai[2];
        float q3 = ar[3]*ar[3] + ai[3]*ai[3];
        float q4 = ar[4]*ar[4] + ai[4]*ai[4];
        float q5 = ar[5]*ar[5] + ai[5]*ai[5];
        float q6 = ar[6]*ar[6] + ai[6]*ai[6];
        float q7 = ar[7]*ar[7] + ai[7]*ai[7];
        float lo = q0 + q1 + q2 + q3;
        float hi = q4 + q5 + q6 + q7;
        float S  = lo + hi;

        float e[8];
        e[0] = (lane & 1) ? (hi - lo) : (lo - hi);   // CNOT(7,0) folded
        e[1] = (q0 + q1 + q4 + q5) - (q2 + q3 + q6 + q7);
        e[2] = (q0 + q2 + q4 + q6) - (q1 + q3 + q5 + q7);
        e[3] = (lane & 16) ? -S : S;
        e[4] = (lane & 8)  ? -S : S;
        e[5] = (lane & 4)  ? -S : S;
        e[6] = (lane & 2)  ? -S : S;
        e[7] = (lane & 1)  ? -S : S;

        // ---- reduce-scatter: lane group g ends with full sum of e[g] ----
        float f4[4];
        {
            bool hb = (lane & 16) != 0;
            #pragma unroll
            for (int k = 0; k < 4; ++k) {
                float send = hb ? e[k] : e[k + 4];
                float recv = __shfl_xor_sync(FULL, send, 16);
                f4[k] = (hb ? e[k + 4] : e[k]) + recv;
            }
        }
        float f2[2];
        {
            bool hb = (lane & 8) != 0;
            #pragma unroll
            for (int k = 0; k < 2; ++k) {
                float send = hb ? f4[k] : f4[k + 2];
                float recv = __shfl_xor_sync(FULL, send, 8);
                f2[k] = (hb ? f4[k + 2] : f4[k]) + recv;
            }
        }
        float ev;
        {
            bool hb = (lane & 4) != 0;
            float send = hb ? f2[0] : f2[1];
            float recv = __shfl_xor_sync(FULL, send, 4);
            ev = (hb ? f2[1] : f2[0]) + recv;
        }
        ev += __shfl_xor_sync(FULL, ev, 2);
        ev += __shfl_xor_sync(FULL, ev, 1);
        // now lane holds e[g], g = (lane>>2)&7

        int buf = t & 1;
        if ((lane & 3) == 0) sh_e[buf][cid][g] = ev;
        __syncthreads();

        // ---- LSTM cell update (each warp redundantly; lane owns index g) ----
        float ef = sh_e[buf][0][g];
        float ei = sh_e[buf][1][g];
        float eg = sh_e[buf][2][g];
        float eo = sh_e[buf][3][g];
        float fv = fast_sigmoid(ef);
        float iv = fast_sigmoid(ei);
        float gv = fast_tanh(eg);
        float ov = fast_sigmoid(eo);
        c_reg = fv * c_reg + iv * gv;
        h_reg = ov * fast_tanh(c_reg);

        if (cid == 0 && (lane & 3) == 0)
            out[(t * BATCH + b) * NQ + g] = h_reg;
    }

    if (cid == 0 && (lane & 3) == 0) {
        out[T_STEPS * BATCH * NQ + b * NQ + g]              = h_reg;  // hx
        out[T_STEPS * BATCH * NQ + BATCH * NQ + b * NQ + g] = c_reg;  // cx
    }
}

// ---------------------------------------------------------------------------
extern "C" void kernel_launch(void* const* d_in, const int* in_sizes, int n_in,
                              void* d_out, int out_size) {
    const float* x  = (const float*)d_in[0];  // inputs [32,128,64]
    const float* W  = (const float*)d_in[1];  // [16,72]
    const float* bv = (const float*)d_in[2];  // [16]
    const float* fp = (const float*)d_in[3];
    const float* ip = (const float*)d_in[4];
    const float* up = (const float*)d_in[5];
    const float* op = (const float*)d_in[6];
    float* out = (float*)d_out;

    qx_kernel<<<(T_STEPS * BATCH) / 8, 64>>>(x, W, bv);
    qlstm_kernel<<<BATCH, 128>>>(W, fp, ip, up, op, out);
}

// round 3
// speedup vs baseline: 4.6229x; 3.3877x over previous
#include <cuda_runtime.h>
#include <math.h>

#define FULL 0xffffffffu
#define T_STEPS 32
#define BATCH   128
#define NQ      8

// Closed-form QLSTM:
// The variational circuit (RX product state; staircase RY(w)+CNOT(w,w+1); ring wrap)
// has exact expectations:
//   <Z_w> = prod_{k=0..w} cos(theta_k) * cos(q_k)   for w = 1..7
//   <Z_0> = prod_{k=1..7} cos(theta_k) * cos(q_k)      (wrap CNOT folded: Z_0 -> Z_7 Z_0)
// where q_k = (W [x;h] + b)_k. Derivation: active-qubit density-matrix flow; the RX
// phases keep the off-diagonal purely imaginary, real RYs preserve it, and the CNOT
// attach step reads only the diagonal -> scalar Bloch-z recursion z *= cos(x)cos(theta).

__device__ __forceinline__ float tanh_ap(float x) {
    float y;
    asm("tanh.approx.f32 %0, %1;" : "=f"(y) : "f"(x));
    return y;
}

// one warp per batch lane. lane = c*8 + j : c = circuit (0=f,1=i,2=g,3=o), j = hidden unit
__global__ void __launch_bounds__(32, 1) qlstm_kernel(
    const float* __restrict__ x,   // [32,128,64]
    const float* __restrict__ W,   // [16,72] row stride 72
    const float* __restrict__ bv,  // [16]
    const float* __restrict__ fp, const float* __restrict__ ip,
    const float* __restrict__ up, const float* __restrict__ op,
    float* __restrict__ out) {

    int lane = threadIdx.x;
    int b    = blockIdx.x;
    int c    = lane >> 3;
    int j    = lane & 7;
    int gb   = lane & 24;      // base lane of this circuit's 8-lane group

    // W[j][16c .. 16c+15] : this lane's slice of the x-projection
    float wx[16];
    #pragma unroll
    for (int m = 0; m < 16; ++m) wx[m] = W[j * 72 + 16 * c + m];
    // W[j][64..71] : h-projection row (full, per lane)
    float wh[8];
    #pragma unroll
    for (int k = 0; k < 8; ++k) wh[k] = W[j * 72 + 64 + k];
    float bj = bv[j];

    // per-circuit variational cos(theta_j), full angle, accurate (computed once)
    const float* Pp = (c == 0) ? fp : (c == 1) ? ip : (c == 2) ? up : op;
    float pct = cosf(Pp[j]);

    float h = 0.f, cstate = 0.f;

    // prefetch x slice for t = 0
    const float4* xp = (const float4*)(x + b * 64 + 16 * c);
    float4 v0 = xp[0], v1 = xp[1], v2 = xp[2], v3 = xp[3];

    #pragma unroll 1
    for (int t = 0; t < T_STEPS; ++t) {
        // ---- x-projection partial: 16-wide dot over this lane's k-slice ----
        float p0 = wx[0]  * v0.x + wx[1]  * v0.y + wx[2]  * v0.z + wx[3]  * v0.w;
        float p1 = wx[4]  * v1.x + wx[5]  * v1.y + wx[6]  * v1.z + wx[7]  * v1.w;
        float p2 = wx[8]  * v2.x + wx[9]  * v2.y + wx[10] * v2.z + wx[11] * v2.w;
        float p3 = wx[12] * v3.x + wx[13] * v3.y + wx[14] * v3.z + wx[15] * v3.w;
        float part = (p0 + p1) + (p2 + p3);

        // prefetch next step's x slice (latency hidden under compute below)
        int tn = (t + 1 < T_STEPS) ? t + 1 : t;
        const float4* xn = (const float4*)(x + (tn * BATCH + b) * 64 + 16 * c);
        v0 = xn[0]; v1 = xn[1]; v2 = xn[2]; v3 = xn[3];

        // reduce partials across the 4 circuit groups (k-slices) -> full x dot, replicated
        part += __shfl_xor_sync(FULL, part, 8);
        part += __shfl_xor_sync(FULL, part, 16);

        // ---- add bias + h-projection ----
        float th = part + bj;
        #pragma unroll
        for (int k = 0; k < 8; ++k)
            th += wh[k] * __shfl_sync(FULL, h, gb | k);

        // ---- circuit expectation: P_j = cos(theta_j) * cos(q_j), prefix products ----
        float P = pct * __cosf(th);
        float A = P;                       // inclusive prefix prod_{k<=j} P_k
        float B = (j == 0) ? 1.f : P;      // same but skipping k=0 (for the wrap correlator)
        {
            float a = __shfl_up_sync(FULL, A, 1);
            float bb = __shfl_up_sync(FULL, B, 1);
            if (j >= 1) { A *= a; B *= bb; }
        }
        {
            float a = __shfl_up_sync(FULL, A, 2);
            float bb = __shfl_up_sync(FULL, B, 2);
            if (j >= 2) { A *= a; B *= bb; }
        }
        {
            float a = __shfl_up_sync(FULL, A, 4);
            float bb = __shfl_up_sync(FULL, B, 4);
            if (j >= 4) { A *= a; B *= bb; }
        }
        float eB = __shfl_sync(FULL, B, gb | 7);   // prod_{k=1..7} P_k
        float ev = (j == 0) ? eB : A;              // <Z_j> for this circuit

        // ---- gate nonlinearity: sigmoid for c in {0,1,3}, tanh for c == 2 ----
        float arg = (c == 2) ? ev : 0.5f * ev;
        float tv  = tanh_ap(arg);
        float v   = (c == 2) ? tv : 0.5f + 0.5f * tv;

        // ---- gather f, i, g, o across circuit groups (j fixed) ----
        float va = __shfl_xor_sync(FULL, v, 8);    // circuit c^1
        float vb = __shfl_xor_sync(FULL, v, 16);   // circuit c^2
        float vc = __shfl_xor_sync(FULL, va, 16);  // circuit c^3
        float f = (c == 0) ? v  : (c == 1) ? va : (c == 2) ? vb : vc;
        float i = (c == 0) ? va : (c == 1) ? v  : (c == 2) ? vc : vb;
        float g = (c == 0) ? vb : (c == 1) ? vc : (c == 2) ? v  : va;
        float o = (c == 0) ? vc : (c == 1) ? vb : (c == 2) ? va : v;

        // ---- LSTM cell ----
        cstate = f * cstate + i * g;
        h = o * tanh_ap(cstate);

        if (c == 0) out[(t * BATCH + b) * NQ + j] = h;
    }

    if (c == 0) {
        out[T_STEPS * BATCH * NQ + b * NQ + j]              = h;       // hx
        out[T_STEPS * BATCH * NQ + BATCH * NQ + b * NQ + j] = cstate;  // cx
    }
}

extern "C" void kernel_launch(void* const* d_in, const int* in_sizes, int n_in,
                              void* d_out, int out_size) {
    const float* x  = (const float*)d_in[0];
    const float* W  = (const float*)d_in[1];
    const float* bv = (const float*)d_in[2];
    const float* fp = (const float*)d_in[3];
    const float* ip = (const float*)d_in[4];
    const float* up = (const float*)d_in[5];
    const float* op = (const float*)d_in[6];
    float* out = (float*)d_out;

    qlstm_kernel<<<BATCH, 32>>>(x, W, bv, fp, ip, up, op, out);
}

// round 4
// speedup vs baseline: 4.7229x; 1.0216x over previous
#include <cuda_runtime.h>
#include <math.h>

#define FULL 0xffffffffu
#define T_STEPS 32
#define BATCH   128
#define NQ      8

// Closed-form QLSTM (derived R2, verified):
//   <Z_w> = prod_{k=0..w} cos(theta_k) * cos(q_k)   for w = 1..7
//   <Z_0> = prod_{k=1..7} cos(theta_k) * cos(q_k)
// with q = W [x;h] + b (first 8 rows only).

__device__ __forceinline__ float tanh_ap(float x) {
    float y;
    asm("tanh.approx.f32 %0, %1;" : "=f"(y) : "f"(x));
    return y;
}

// one warp per batch element. lane = c*8 + j : c = circuit (0=f,1=i,2=g,3=o), j = hidden unit
__global__ void __launch_bounds__(32, 1) qlstm_kernel(
    const float* __restrict__ x,   // [32,128,64]
    const float* __restrict__ W,   // [16,72]
    const float* __restrict__ bv,  // [16]
    const float* __restrict__ fp, const float* __restrict__ ip,
    const float* __restrict__ up, const float* __restrict__ op,
    float* __restrict__ out) {

    __shared__ float s_qx[T_STEPS * NQ];

    int lane = threadIdx.x;
    int b    = blockIdx.x;
    int c    = lane >> 3;
    int j    = lane & 7;
    int gb   = lane & 24;      // base lane of this circuit's 8-lane group

    // ---- weights ----
    float wx[16];
    #pragma unroll
    for (int m = 0; m < 16; ++m) wx[m] = W[j * 72 + 16 * c + m];
    float wh[8];
    #pragma unroll
    for (int k = 0; k < 8; ++k) wh[k] = W[j * 72 + 64 + k];
    float bj = bv[j];

    const float* Pp = (c == 0) ? fp : (c == 1) ? ip : (c == 2) ? up : op;
    float pct = cosf(Pp[j]);

    // ---- prologue: precompute qx[t][j] = b_j + W_x[j,:].x[t,b,:] for all t ----
    // (independent of h; bulk-parallel, MLP-overlapped loads)
    #pragma unroll 8
    for (int t = 0; t < T_STEPS; ++t) {
        const float4* xp = (const float4*)(x + (t * BATCH + b) * 64 + 16 * c);
        float4 v0 = xp[0], v1 = xp[1], v2 = xp[2], v3 = xp[3];
        float p0 = wx[0]  * v0.x + wx[1]  * v0.y + wx[2]  * v0.z + wx[3]  * v0.w;
        float p1 = wx[4]  * v1.x + wx[5]  * v1.y + wx[6]  * v1.z + wx[7]  * v1.w;
        float p2 = wx[8]  * v2.x + wx[9]  * v2.y + wx[10] * v2.z + wx[11] * v2.w;
        float p3 = wx[12] * v3.x + wx[13] * v3.y + wx[14] * v3.z + wx[15] * v3.w;
        float part = (p0 + p1) + (p2 + p3);
        part += __shfl_xor_sync(FULL, part, 8);
        part += __shfl_xor_sync(FULL, part, 16);
        if (c == 0) s_qx[t * NQ + j] = part + bj;
    }
    __syncwarp();

    // prefix-mask predicates (constant over the loop): include g0 iff j>0;
    // include g_k (k>=1) iff (j==0 || k<=j)
    bool j0 = (j == 0);
    bool m1 = j0 || (1 <= j), m2 = j0 || (2 <= j), m3 = j0 || (3 <= j);
    bool m4 = j0 || (4 <= j), m5 = j0 || (5 <= j), m6 = j0 || (6 <= j);

    float h = 0.f, cstate = 0.f;

    #pragma unroll 1
    for (int t = 0; t < T_STEPS; ++t) {
        // LDS early — off the h-critical path
        float qx = s_qx[t * NQ + j];

        // ---- th_j = qx_j + Wh[j,:] . h : parallel broadcast fan + mult-add tree ----
        float h0 = __shfl_sync(FULL, h, gb | 0);
        float h1 = __shfl_sync(FULL, h, gb | 1);
        float h2 = __shfl_sync(FULL, h, gb | 2);
        float h3 = __shfl_sync(FULL, h, gb | 3);
        float h4 = __shfl_sync(FULL, h, gb | 4);
        float h5 = __shfl_sync(FULL, h, gb | 5);
        float h6 = __shfl_sync(FULL, h, gb | 6);
        float h7 = __shfl_sync(FULL, h, gb | 7);
        float s01 = wh[0] * h0 + wh[1] * h1;
        float s23 = wh[2] * h2 + wh[3] * h3;
        float s45 = wh[4] * h4 + wh[5] * h5;
        float s67 = wh[6] * h6 + wh[7] * h7;
        float th  = (qx + (s01 + s23)) + (s45 + s67);

        // ---- P_j = cos(theta_j) * cos(q_j) ----
        float P = pct * __cosf(th);

        // ---- parallel gather of all 8 P's in this circuit group ----
        float g0 = __shfl_sync(FULL, P, gb | 0);
        float g1 = __shfl_sync(FULL, P, gb | 1);
        float g2 = __shfl_sync(FULL, P, gb | 2);
        float g3 = __shfl_sync(FULL, P, gb | 3);
        float g4 = __shfl_sync(FULL, P, gb | 4);
        float g5 = __shfl_sync(FULL, P, gb | 5);
        float g6 = __shfl_sync(FULL, P, gb | 6);
        float g7 = __shfl_sync(FULL, P, gb | 7);

        // masked product tree: ev = <Z_j> (prefix prod; j==0 gets the wrap correlator)
        float a0 = j0 ? 1.f : g0;
        float a1 = m1 ? g1 : 1.f;
        float a2 = m2 ? g2 : 1.f;
        float a3 = m3 ? g3 : 1.f;
        float a4 = m4 ? g4 : 1.f;
        float a5 = m5 ? g5 : 1.f;
        float a6 = m6 ? g6 : 1.f;
        float a7 = (j0 || j == 7) ? g7 : 1.f;
        float ev = ((a0 * a1) * (a2 * a3)) * ((a4 * a5) * (a6 * a7));

        // ---- nonlinearity: sigmoid (c!=2) / tanh (c==2) ----
        float arg = (c == 2) ? ev : 0.5f * ev;
        float tv  = tanh_ap(arg);
        float v   = (c == 2) ? tv : fmaf(0.5f, tv, 0.5f);

        // ---- gather f,i,g,o: three independent xor-shuffles ----
        float va = __shfl_xor_sync(FULL, v, 8);    // circuit c^1
        float vb = __shfl_xor_sync(FULL, v, 16);   // circuit c^2
        float vc = __shfl_xor_sync(FULL, v, 24);   // circuit c^3
        float f = (c == 0) ? v  : (c == 1) ? va : (c == 2) ? vb : vc;
        float i = (c == 0) ? va : (c == 1) ? v  : (c == 2) ? vc : vb;
        float g = (c == 0) ? vb : (c == 1) ? vc : (c == 2) ? v  : va;
        float o = (c == 0) ? vc : (c == 1) ? vb : (c == 2) ? va : v;

        // ---- LSTM cell ----
        cstate = f * cstate + i * g;
        h = o * tanh_ap(cstate);

        if (c == 0) out[(t * BATCH + b) * NQ + j] = h;
    }

    if (c == 0) {
        out[T_STEPS * BATCH * NQ + b * NQ + j]              = h;       // hx
        out[T_STEPS * BATCH * NQ + BATCH * NQ + b * NQ + j] = cstate;  // cx
    }
}

extern "C" void kernel_launch(void* const* d_in, const int* in_sizes, int n_in,
                              void* d_out, int out_size) {
    const float* x  = (const float*)d_in[0];
    const float* W  = (const float*)d_in[1];
    const float* bv = (const float*)d_in[2];
    const float* fp = (const float*)d_in[3];
    const float* ip = (const float*)d_in[4];
    const float* up = (const float*)d_in[5];
    const float* op = (const float*)d_in[6];
    float* out = (float*)d_out;

    qlstm_kernel<<<BATCH, 32>>>(x, W, bv, fp, ip, up, op, out);
}

// round 5
// speedup vs baseline: 4.8381x; 1.0244x over previous
#include <cuda_runtime.h>
#include <math.h>

#define FULL 0xffffffffu
#define T_STEPS 32
#define BATCH   128
#define NQ      8

// Closed-form QLSTM (derived R2, verified):
//   <Z_w> = prod_{k=0..w} cos(theta_k) * cos(q_k)   for w = 1..7
//   <Z_0> = prod_{k=1..7} cos(theta_k) * cos(q_k)
// with q = W [x;h] + b (first 8 rows only). Separable:
//   <Z_j> = Cpref_j * (masked prod of cos q), Cpref_j = matching prod of cos(theta).

__device__ __forceinline__ float tanh_ap(float x) {
    float y;
    asm("tanh.approx.f32 %0, %1;" : "=f"(y) : "f"(x));
    return y;
}

// one warp per batch element. lane = c*8 + j : c = circuit (0=f,1=i,2=g,3=o), j = hidden unit
__global__ void __launch_bounds__(32, 1) qlstm_kernel(
    const float* __restrict__ x,   // [32,128,64]
    const float* __restrict__ W,   // [16,72]
    const float* __restrict__ bv,  // [16]
    const float* __restrict__ fp, const float* __restrict__ ip,
    const float* __restrict__ up, const float* __restrict__ op,
    float* __restrict__ out) {

    int lane = threadIdx.x;
    int b    = blockIdx.x;
    int c    = lane >> 3;
    int j    = lane & 7;
    int gb   = lane & 24;      // base lane of this circuit's 8-lane group

    // ---- weights ----
    float wx[16];
    #pragma unroll
    for (int m = 0; m < 16; ++m) wx[m] = W[j * 72 + 16 * c + m];
    float wh[8];
    #pragma unroll
    for (int k = 0; k < 8; ++k) wh[k] = W[j * 72 + 64 + k];
    float bj = bv[j];

    // per-lane theta prefix constant Cpref_j (time-invariant)
    const float* Pp = (c == 0) ? fp : (c == 1) ? ip : (c == 2) ? up : op;
    bool j0 = (j == 0);
    float Cpref = 1.f;
    #pragma unroll
    for (int k = 0; k < 8; ++k) {
        bool incl = j0 ? (k >= 1) : (k <= j);
        if (incl) Cpref *= cosf(Pp[k]);
    }

    // loop-invariant inclusion masks for the dynamic cos-q product
    bool m0 = !j0;                     // include k=0 iff j>0
    bool m1 = true;                    // k=1 always (j0 wrap includes 1..7; j>=1 includes 1)
    bool m2 = j0 || (2 <= j), m3 = j0 || (3 <= j), m4 = j0 || (4 <= j);
    bool m5 = j0 || (5 <= j), m6 = j0 || (6 <= j), m7 = j0 || (j == 7);

    // ---- qx for t = 0 ----
    float qx_cur;
    {
        const float4* xp = (const float4*)(x + b * 64 + 16 * c);
        float4 v0 = xp[0], v1 = xp[1], v2 = xp[2], v3 = xp[3];
        float p0 = wx[0]  * v0.x + wx[1]  * v0.y + wx[2]  * v0.z + wx[3]  * v0.w;
        float p1 = wx[4]  * v1.x + wx[5]  * v1.y + wx[6]  * v1.z + wx[7]  * v1.w;
        float p2 = wx[8]  * v2.x + wx[9]  * v2.y + wx[10] * v2.z + wx[11] * v2.w;
        float p3 = wx[12] * v3.x + wx[13] * v3.y + wx[14] * v3.z + wx[15] * v3.w;
        float part = (p0 + p1) + (p2 + p3);
        part += __shfl_xor_sync(FULL, part, 8);
        part += __shfl_xor_sync(FULL, part, 16);
        qx_cur = part + bj;
    }

    float h = 0.f, cstate = 0.f;

    #pragma unroll 1
    for (int t = 0; t < T_STEPS; ++t) {
        // ======== OFF-CHAIN: pipeline next step's x-projection (fills stall shadows)
        int tn = (t + 1 < T_STEPS) ? t + 1 : t;
        const float4* xp = (const float4*)(x + (tn * BATCH + b) * 64 + 16 * c);
        float4 v0 = xp[0], v1 = xp[1], v2 = xp[2], v3 = xp[3];

        // ======== CHAIN: h fan-out ========
        float h0 = __shfl_sync(FULL, h, gb | 0);
        float h1 = __shfl_sync(FULL, h, gb | 1);
        float h2 = __shfl_sync(FULL, h, gb | 2);
        float h3 = __shfl_sync(FULL, h, gb | 3);
        float h4 = __shfl_sync(FULL, h, gb | 4);
        float h5 = __shfl_sync(FULL, h, gb | 5);
        float h6 = __shfl_sync(FULL, h, gb | 6);
        float h7 = __shfl_sync(FULL, h, gb | 7);
        float s01 = wh[0] * h0 + wh[1] * h1;
        float s23 = wh[2] * h2 + wh[3] * h3;
        float s45 = wh[4] * h4 + wh[5] * h5;
        float s67 = wh[6] * h6 + wh[7] * h7;
        float th  = (qx_cur + (s01 + s23)) + (s45 + s67);

        // cos of the full angle q_j
        float cq = __cosf(th);

        // off-chain continued: next-step dot partials
        float p0 = wx[0]  * v0.x + wx[1]  * v0.y + wx[2]  * v0.z + wx[3]  * v0.w;
        float p1 = wx[4]  * v1.x + wx[5]  * v1.y + wx[6]  * v1.z + wx[7]  * v1.w;
        float p2 = wx[8]  * v2.x + wx[9]  * v2.y + wx[10] * v2.z + wx[11] * v2.w;
        float p3 = wx[12] * v3.x + wx[13] * v3.y + wx[14] * v3.z + wx[15] * v3.w;
        float pp = (p0 + p1) + (p2 + p3);

        // ======== CHAIN: gather cos q across the circuit group ========
        float g0 = __shfl_sync(FULL, cq, gb | 0);
        float g1 = __shfl_sync(FULL, cq, gb | 1);
        float g2 = __shfl_sync(FULL, cq, gb | 2);
        float g3 = __shfl_sync(FULL, cq, gb | 3);
        float g4 = __shfl_sync(FULL, cq, gb | 4);
        float g5 = __shfl_sync(FULL, cq, gb | 5);
        float g6 = __shfl_sync(FULL, cq, gb | 6);
        float g7 = __shfl_sync(FULL, cq, gb | 7);

        float a0 = m0 ? g0 : 1.f;
        float a1 = m1 ? g1 : 1.f;
        float a2 = m2 ? g2 : 1.f;
        float a3 = m3 ? g3 : 1.f;
        float a4 = m4 ? g4 : 1.f;
        float a5 = m5 ? g5 : 1.f;
        float a6 = m6 ? g6 : 1.f;
        float a7 = m7 ? g7 : 1.f;
        float ev = Cpref * (((a0 * a1) * (a2 * a3)) * ((a4 * a5) * (a6 * a7)));

        // nonlinearity: sigmoid (c!=2) / tanh (c==2)
        float arg = (c == 2) ? ev : 0.5f * ev;
        float tv  = tanh_ap(arg);
        float v   = (c == 2) ? tv : fmaf(0.5f, tv, 0.5f);

        // off-chain: finish next-step qx reduction (independent shuffles)
        pp += __shfl_xor_sync(FULL, pp, 8);
        pp += __shfl_xor_sync(FULL, pp, 16);

        // ======== CHAIN: f,i,g,o via 4 parallel index shuffles (no selects) ========
        float f = __shfl_sync(FULL, v, j);
        float i = __shfl_sync(FULL, v, 8  | j);
        float g = __shfl_sync(FULL, v, 16 | j);
        float o = __shfl_sync(FULL, v, 24 | j);

        cstate = f * cstate + i * g;
        h = o * tanh_ap(cstate);

        qx_cur = pp + bj;

        if (c == 0) out[(t * BATCH + b) * NQ + j] = h;
    }

    if (c == 0) {
        out[T_STEPS * BATCH * NQ + b * NQ + j]              = h;       // hx
        out[T_STEPS * BATCH * NQ + BATCH * NQ + b * NQ + j] = cstate;  // cx
    }
}

extern "C" void kernel_launch(void* const* d_in, const int* in_sizes, int n_in,
                              void* d_out, int out_size) {
    const float* x  = (const float*)d_in[0];
    const float* W  = (const float*)d_in[1];
    const float* bv = (const float*)d_in[2];
    const float* fp = (const float*)d_in[3];
    const float* ip = (const float*)d_in[4];
    const float* up = (const float*)d_in[5];
    const float* op = (const float*)d_in[6];
    float* out = (float*)d_out;

    qlstm_kernel<<<BATCH, 32>>>(x, W, bv, fp, ip, up, op, out);
}

// round 6
// speedup vs baseline: 5.8656x; 1.2124x over previous
#include <cuda_runtime.h>
#include <math.h>

#define FULL 0xffffffffu
#define T_STEPS 32
#define BATCH   128
#define NQ      8

// Closed-form QLSTM (derived R2, verified):
//   <Z_w> = prod_{k=0..w} cos(theta_k) * cos(q_k)   for w = 1..7
//   <Z_0> = prod_{k=1..7} cos(theta_k) * cos(q_k)
// with q = W [x;h] + b (first 8 rows only). Separable: theta part folded into
// per-lane constant Cpref; per step only masked products of cos(q) are dynamic.

__device__ __forceinline__ float tanh_ap(float x) {
    float y;
    asm("tanh.approx.f32 %0, %1;" : "=f"(y) : "f"(x));
    return y;
}

// Block = 160 threads. Warp 0: recurrence (lane = c*8+j). Warps 1-4: producers,
// warp w precomputes qx[t][j] for t in [(w-1)*8, w*8) into shared memory.
__global__ void __launch_bounds__(160, 1) qlstm_kernel(
    const float* __restrict__ x,   // [32,128,64]
    const float* __restrict__ W,   // [16,72]
    const float* __restrict__ bv,  // [16]
    const float* __restrict__ fp, const float* __restrict__ ip,
    const float* __restrict__ up, const float* __restrict__ op,
    float* __restrict__ out) {

    __shared__ float s_qx[T_STEPS * NQ];

    int tid  = threadIdx.x;
    int lane = tid & 31;
    int wid  = tid >> 5;
    int b    = blockIdx.x;
    int c    = lane >> 3;
    int j    = lane & 7;
    int gb   = lane & 24;

    if (wid >= 1) {
        // ---- producer warps: qx[t][j] = b_j + W_x[j,:] . x[t,b,:] ----
        float wx[16];
        #pragma unroll
        for (int m = 0; m < 16; ++m) wx[m] = W[j * 72 + 16 * c + m];
        float bj = bv[j];
        int t0 = (wid - 1) * 8;
        #pragma unroll
        for (int tt = 0; tt < 8; ++tt) {
            int t = t0 + tt;
            const float4* xp = (const float4*)(x + (t * BATCH + b) * 64 + 16 * c);
            float4 v0 = xp[0], v1 = xp[1], v2 = xp[2], v3 = xp[3];
            float p0 = wx[0]  * v0.x + wx[1]  * v0.y + wx[2]  * v0.z + wx[3]  * v0.w;
            float p1 = wx[4]  * v1.x + wx[5]  * v1.y + wx[6]  * v1.z + wx[7]  * v1.w;
            float p2 = wx[8]  * v2.x + wx[9]  * v2.y + wx[10] * v2.z + wx[11] * v2.w;
            float p3 = wx[12] * v3.x + wx[13] * v3.y + wx[14] * v3.z + wx[15] * v3.w;
            float part = (p0 + p1) + (p2 + p3);
            part += __shfl_xor_sync(FULL, part, 8);
            part += __shfl_xor_sync(FULL, part, 16);
            if (c == 0) s_qx[t * NQ + j] = part + bj;
        }
    }

    // ---- recurrence warp setup (overlaps producer work) ----
    float wh[8];
    float Cpref = 1.f;
    bool  m0 = false, m2 = false, m3 = false, m4 = false, m5 = false, m6 = false, m7 = false;
    if (wid == 0) {
        #pragma unroll
        for (int k = 0; k < 8; ++k) wh[k] = W[j * 72 + 64 + k];
        const float* Pp = (c == 0) ? fp : (c == 1) ? ip : (c == 2) ? up : op;
        bool j0 = (j == 0);
        #pragma unroll
        for (int k = 0; k < 8; ++k) {
            bool incl = j0 ? (k >= 1) : (k <= j);
            if (incl) Cpref *= cosf(Pp[k]);
        }
        m0 = !j0;
        m2 = j0 || (2 <= j); m3 = j0 || (3 <= j); m4 = j0 || (4 <= j);
        m5 = j0 || (5 <= j); m6 = j0 || (6 <= j); m7 = j0 || (j == 7);
    }

    __syncthreads();   // all qx ready

    if (wid != 0) return;

    float h = 0.f, cstate = 0.f;
    float qx_cur = s_qx[j];     // t = 0

    #pragma unroll 1
    for (int t = 0; t < T_STEPS; ++t) {
        // prefetch next step's qx (off-chain LDS)
        int tn = (t + 1 < T_STEPS) ? t + 1 : t;
        float qx_next = s_qx[tn * NQ + j];

        // ---- CHAIN: h fan-out + dot ----
        float h0 = __shfl_sync(FULL, h, gb | 0);
        float h1 = __shfl_sync(FULL, h, gb | 1);
        float h2 = __shfl_sync(FULL, h, gb | 2);
        float h3 = __shfl_sync(FULL, h, gb | 3);
        float h4 = __shfl_sync(FULL, h, gb | 4);
        float h5 = __shfl_sync(FULL, h, gb | 5);
        float h6 = __shfl_sync(FULL, h, gb | 6);
        float h7 = __shfl_sync(FULL, h, gb | 7);
        float s01 = wh[0] * h0 + wh[1] * h1;
        float s23 = wh[2] * h2 + wh[3] * h3;
        float s45 = wh[4] * h4 + wh[5] * h5;
        float s67 = wh[6] * h6 + wh[7] * h7;
        float th  = (qx_cur + (s01 + s23)) + (s45 + s67);

        float cq = __cosf(th);

        // ---- CHAIN: gather cos q across the circuit group ----
        float g0 = __shfl_sync(FULL, cq, gb | 0);
        float g1 = __shfl_sync(FULL, cq, gb | 1);
        float g2 = __shfl_sync(FULL, cq, gb | 2);
        float g3 = __shfl_sync(FULL, cq, gb | 3);
        float g4 = __shfl_sync(FULL, cq, gb | 4);
        float g5 = __shfl_sync(FULL, cq, gb | 5);
        float g6 = __shfl_sync(FULL, cq, gb | 6);
        float g7 = __shfl_sync(FULL, cq, gb | 7);

        float a0 = m0 ? g0 : 1.f;
        float a2 = m2 ? g2 : 1.f;
        float a3 = m3 ? g3 : 1.f;
        float a4 = m4 ? g4 : 1.f;
        float a5 = m5 ? g5 : 1.f;
        float a6 = m6 ? g6 : 1.f;
        float a7 = m7 ? g7 : 1.f;
        float ev = Cpref * (((a0 * g1) * (a2 * a3)) * ((a4 * a5) * (a6 * a7)));

        // ---- nonlinearity: sigmoid (c!=2) / tanh (c==2) ----
        float arg = (c == 2) ? ev : 0.5f * ev;
        float tv  = tanh_ap(arg);
        float v   = (c == 2) ? tv : fmaf(0.5f, tv, 0.5f);

        // ---- CHAIN: f,i,g,o via 4 parallel index shuffles ----
        float f = __shfl_sync(FULL, v, j);
        float i = __shfl_sync(FULL, v, 8  | j);
        float g = __shfl_sync(FULL, v, 16 | j);
        float o = __shfl_sync(FULL, v, 24 | j);

        cstate = f * cstate + i * g;
        h = o * tanh_ap(cstate);

        qx_cur = qx_next;

        if (c == 0) out[(t * BATCH + b) * NQ + j] = h;
    }

    if (c == 0) {
        out[T_STEPS * BATCH * NQ + b * NQ + j]              = h;       // hx
        out[T_STEPS * BATCH * NQ + BATCH * NQ + b * NQ + j] = cstate;  // cx
    }
}

extern "C" void kernel_launch(void* const* d_in, const int* in_sizes, int n_in,
                              void* d_out, int out_size) {
    const float* x  = (const float*)d_in[0];
    const float* W  = (const float*)d_in[1];
    const float* bv = (const float*)d_in[2];
    const float* fp = (const float*)d_in[3];
    const float* ip = (const float*)d_in[4];
    const float* up = (const float*)d_in[5];
    const float* op = (const float*)d_in[6];
    float* out = (float*)d_out;

    qlstm_kernel<<<BATCH, 160>>>(x, W, bv, fp, ip, up, op, out);
}

// round 7
// speedup vs baseline: 6.7975x; 1.1589x over previous
#include <cuda_runtime.h>
#include <math.h>

#define FULL 0xffffffffu
#define T_STEPS 32
#define BATCH   128
#define NQ      8

// Closed-form QLSTM (derived R2, verified):
//   <Z_w> = prod_{k=0..w} cos(theta_k) * cos(q_k)   for w = 1..7
//   <Z_0> = prod_{k=1..7} cos(theta_k) * cos(q_k)
// q = W [x;h] + b (first 8 rows). Separable: theta prefix folded into per-lane
// Cpref (with the sigmoid 1/2 folded in for c != 2).

__device__ __forceinline__ float tanh_ap(float x) {
    float y;
    asm("tanh.approx.f32 %0, %1;" : "=f"(y) : "f"(x));
    return y;
}

__device__ __forceinline__ void bar_arrive(int id, int cnt) {
    asm volatile("bar.arrive %0, %1;" :: "r"(id), "r"(cnt));
}
__device__ __forceinline__ void bar_sync_named(int id, int cnt) {
    asm volatile("bar.sync %0, %1;" :: "r"(id), "r"(cnt) : "memory");
}

// Block = 160 threads. Warp 0: recurrence (lane = c*8+j). Warps 1-4: producers;
// warp w computes qx[t][j] for t in [(w-1)*8, w*8), arrives on named barrier w.
__global__ void __launch_bounds__(160, 1) qlstm_kernel(
    const float* __restrict__ x,   // [32,128,64]
    const float* __restrict__ W,   // [16,72]
    const float* __restrict__ bv,  // [16]
    const float* __restrict__ fp, const float* __restrict__ ip,
    const float* __restrict__ up, const float* __restrict__ op,
    float* __restrict__ out) {

    __shared__ float s_qx[T_STEPS * NQ];

    int tid  = threadIdx.x;
    int lane = tid & 31;
    int wid  = tid >> 5;
    int b    = blockIdx.x;
    int c    = lane >> 3;
    int j    = lane & 7;
    int gb   = lane & 24;

    if (wid >= 1) {
        // ---- producer warp: qx[t][j] = b_j + W_x[j,:] . x[t,b,:] ----
        const float4* wxp = (const float4*)(W + j * 72 + 16 * c);
        float4 w0 = wxp[0], w1 = wxp[1], w2 = wxp[2], w3 = wxp[3];
        float bj = bv[j];
        int t0 = (wid - 1) * 8;
        #pragma unroll
        for (int tt = 0; tt < 8; ++tt) {
            int t = t0 + tt;
            const float4* xp = (const float4*)(x + (t * BATCH + b) * 64 + 16 * c);
            float4 v0 = xp[0], v1 = xp[1], v2 = xp[2], v3 = xp[3];
            float p0 = w0.x * v0.x + w0.y * v0.y + w0.z * v0.z + w0.w * v0.w;
            float p1 = w1.x * v1.x + w1.y * v1.y + w1.z * v1.z + w1.w * v1.w;
            float p2 = w2.x * v2.x + w2.y * v2.y + w2.z * v2.z + w2.w * v2.w;
            float p3 = w3.x * v3.x + w3.y * v3.y + w3.z * v3.z + w3.w * v3.w;
            float part = (p0 + p1) + (p2 + p3);
            part += __shfl_xor_sync(FULL, part, 8);
            part += __shfl_xor_sync(FULL, part, 16);
            if (c == 0) s_qx[t * NQ + j] = part + bj;
        }
        __threadfence_block();
        bar_arrive(wid, 64);
        return;
    }

    // ---- recurrence warp setup (overlaps producers) ----
    const float4* whp = (const float4*)(W + j * 72 + 64);
    float4 wa = whp[0], wb4 = whp[1];

    bool j0 = (j == 0);
    bool m0 = !j0;
    bool m2 = j0 || (2 <= j), m3 = j0 || (3 <= j), m4 = j0 || (4 <= j);
    bool m5 = j0 || (5 <= j), m6 = j0 || (6 <= j), m7 = j0 || (j == 7);

    // Cpref via one __cosf per lane + fan + masked tree (same shape as per-step)
    const float* Pp = (c == 0) ? fp : (c == 1) ? ip : (c == 2) ? up : op;
    float pct = __cosf(Pp[j]);
    {
        float q0 = __shfl_sync(FULL, pct, gb | 0);
        float q1 = __shfl_sync(FULL, pct, gb | 1);
        float q2 = __shfl_sync(FULL, pct, gb | 2);
        float q3 = __shfl_sync(FULL, pct, gb | 3);
        float q4 = __shfl_sync(FULL, pct, gb | 4);
        float q5 = __shfl_sync(FULL, pct, gb | 5);
        float q6 = __shfl_sync(FULL, pct, gb | 6);
        float q7 = __shfl_sync(FULL, pct, gb | 7);
        float a0 = m0 ? q0 : 1.f;
        float a2 = m2 ? q2 : 1.f;
        float a3 = m3 ? q3 : 1.f;
        float a4 = m4 ? q4 : 1.f;
        float a5 = m5 ? q5 : 1.f;
        float a6 = m6 ? q6 : 1.f;
        float a7 = m7 ? q7 : 1.f;
        pct = ((a0 * q1) * (a2 * a3)) * ((a4 * a5) * (a6 * a7));
    }
    float Cpref = (c == 2) ? pct : 0.5f * pct;   // fold sigmoid 1/2

    float h = 0.f, cstate = 0.f;

    #pragma unroll
    for (int seg = 0; seg < 4; ++seg) {
        bar_sync_named(seg + 1, 64);   // producer warp seg+1 has landed its qx range

        #pragma unroll
        for (int tt = 0; tt < 8; ++tt) {
            int t = seg * 8 + tt;
            // LDS early; first use is ~55 cyc into the chain -> latency hidden
            float qx = s_qx[t * NQ + j];

            // ---- CHAIN: h fan-out + dot ----
            float h0 = __shfl_sync(FULL, h, gb | 0);
            float h1 = __shfl_sync(FULL, h, gb | 1);
            float h2 = __shfl_sync(FULL, h, gb | 2);
            float h3 = __shfl_sync(FULL, h, gb | 3);
            float h4 = __shfl_sync(FULL, h, gb | 4);
            float h5 = __shfl_sync(FULL, h, gb | 5);
            float h6 = __shfl_sync(FULL, h, gb | 6);
            float h7 = __shfl_sync(FULL, h, gb | 7);
            float s01 = wa.x  * h0 + wa.y  * h1;
            float s23 = wa.z  * h2 + wa.w  * h3;
            float s45 = wb4.x * h4 + wb4.y * h5;
            float s67 = wb4.z * h6 + wb4.w * h7;
            float th  = (qx + (s01 + s23)) + (s45 + s67);

            float cq = __cosf(th);

            // ---- CHAIN: gather cos q across the circuit group ----
            float g0 = __shfl_sync(FULL, cq, gb | 0);
            float g1 = __shfl_sync(FULL, cq, gb | 1);
            float g2 = __shfl_sync(FULL, cq, gb | 2);
            float g3 = __shfl_sync(FULL, cq, gb | 3);
            float g4 = __shfl_sync(FULL, cq, gb | 4);
            float g5 = __shfl_sync(FULL, cq, gb | 5);
            float g6 = __shfl_sync(FULL, cq, gb | 6);
            float g7 = __shfl_sync(FULL, cq, gb | 7);

            float a0 = m0 ? g0 : 1.f;
            float a2 = m2 ? g2 : 1.f;
            float a3 = m3 ? g3 : 1.f;
            float a4 = m4 ? g4 : 1.f;
            float a5 = m5 ? g5 : 1.f;
            float a6 = m6 ? g6 : 1.f;
            float a7 = m7 ? g7 : 1.f;
            // Cpref at a leaf: no extra tree depth
            float arg = (((Cpref * a0) * (g1 * a2)) * (a3 * a4)) * ((a5 * a6) * a7);

            // nonlinearity: tanh for c==2; sigmoid = 0.5 + 0.5*tanh(ev/2) (1/2 pre-folded)
            float tv = tanh_ap(arg);
            float v  = (c == 2) ? tv : fmaf(0.5f, tv, 0.5f);

            // ---- CHAIN: f,i,g,o via 4 parallel index shuffles ----
            float f = __shfl_sync(FULL, v, j);
            float i = __shfl_sync(FULL, v, 8  | j);
            float g = __shfl_sync(FULL, v, 16 | j);
            float o = __shfl_sync(FULL, v, 24 | j);

            cstate = fmaf(f, cstate, i * g);
            h = o * tanh_ap(cstate);

            if (c == 0) out[(t * BATCH + b) * NQ + j] = h;
        }
    }

    if (c == 0) {
        out[T_STEPS * BATCH * NQ + b * NQ + j]              = h;       // hx
        out[T_STEPS * BATCH * NQ + BATCH * NQ + b * NQ + j] = cstate;  // cx
    }
}

extern "C" void kernel_launch(void* const* d_in, const int* in_sizes, int n_in,
                              void* d_out, int out_size) {
    const float* x  = (const float*)d_in[0];
    const float* W  = (const float*)d_in[1];
    const float* bv = (const float*)d_in[2];
    const float* fp = (const float*)d_in[3];
    const float* ip = (const float*)d_in[4];
    const float* up = (const float*)d_in[5];
    const float* op = (const float*)d_in[6];
    float* out = (float*)d_out;

    qlstm_kernel<<<BATCH, 160>>>(x, W, bv, fp, ip, up, op, out);
}